// round 13
// baseline (speedup 1.0000x reference)
#include <cuda_runtime.h>

// TemporalDecay: out = h + (1-m)*g*(h_fwd - h),
//   g = exp(-relu(delta*W + b)),  delta integer in [1,4],
//   h_fwd[b,t,j] = h_a[b, t-(delta-1), j]   (<= 3 rows back).
//
// R13: 256-bit global accesses (sm_103a ld/st.global.v8.b32). Each thread
// owns 8 consecutive channels of one (b,t) row: 9x 32B loads + 1x 32B store,
// halving LDG/STG instruction count, L1 wavefront issue and ALU addressing
// per byte vs the 128-bit design that plateaued at 27.5us (R7/R9/R12).
// Bytes-in-flight/SM rises ~16% despite fewer warps. gamma table + PDL kept;
// L2 eviction hints dropped (measured neutral in R12).

static constexpr int Bq = 32, Tq = 2048;
static constexpr int THREADS = 128;
static constexpr int BLOCKS = Bq * Tq * 256 / 8 / THREADS;  // 16384

struct F8 { float v[8]; };

__device__ __forceinline__ F8 ld256(const float* p) {
    F8 r;
    asm("ld.global.nc.v8.b32 {%0,%1,%2,%3,%4,%5,%6,%7}, [%8];"
        : "=f"(r.v[0]), "=f"(r.v[1]), "=f"(r.v[2]), "=f"(r.v[3]),
          "=f"(r.v[4]), "=f"(r.v[5]), "=f"(r.v[6]), "=f"(r.v[7])
        : "l"(p));
    return r;
}
__device__ __forceinline__ void st256(float* p, const F8& x) {
    asm volatile("st.global.v8.b32 [%0], {%1,%2,%3,%4,%5,%6,%7,%8};"
                 :: "l"(p),
                    "f"(x.v[0]), "f"(x.v[1]), "f"(x.v[2]), "f"(x.v[3]),
                    "f"(x.v[4]), "f"(x.v[5]), "f"(x.v[6]), "f"(x.v[7])
                 : "memory");
}

// gamma[d-1][channel]: 4 rows x 256 floats (rows 1..3 read by decay).
__device__ float g_gamma[4 * 256];

__global__ void gamma_precompute_kernel(const float* __restrict__ W,
                                        const float* __restrict__ bias) {
    cudaTriggerProgrammaticLaunchCompletion();
    int j = threadIdx.x;  // 0..255 channel
    float w = W[j];
    float bb = bias[j];
#pragma unroll
    for (int dm = 0; dm < 4; dm++) {
        float x = fmaxf(fmaf((float)(dm + 1), w, bb), 0.0f);
        g_gamma[dm * 256 + j] = __expf(-x);
    }
}

__global__ void __launch_bounds__(THREADS, 6) decay_kernel(
    const float* __restrict__ H,      // h_a  [B*T*256]
    const float* __restrict__ DL,     // deltas [B*T*64]
    const float* __restrict__ MM,     // mask   [B*T*64]
    float* __restrict__ OUT)
{
    const int g    = blockIdx.x * THREADS + threadIdx.x;
    const int col8 = g & 31;          // which 8-channel group of the 256-ch row
    const int r    = g >> 5;          // (b,t) row
    const int t    = r & (Tq - 1);

    const float* Hrow = H + r * 256 + col8 * 8;
    const float* Drow = DL + r * 64 + (col8 & 7) * 8;
    const float* Mrow = MM + r * 64 + (col8 & 7) * 8;

    // halo offsets in floats (clamped; clamped rows never selected: delta<=t+1)
    const int m1 = (t >= 1) ? 256 : 0;
    const int m2 = (t >= 2) ? 512 : m1;
    const int m3 = (t >= 3) ? 768 : m2;

    // --- batched 256-bit loads, all independent (overlap gamma via PDL) ---
    const F8 ha = ld256(Hrow);
    const F8 w1 = ld256(Hrow - m1);
    const F8 w2 = ld256(Hrow - m2);
    const F8 w3 = ld256(Hrow - m3);
    const F8 dl = ld256(Drow);
    const F8 mm = ld256(Mrow);

    // --- gamma table (L1-hot 4KB) after grid dependency ---
    cudaGridDependencySynchronize();
    const float* gbase = g_gamma + col8 * 8;
    const F8 gam1 = ld256(gbase + 1 * 256);
    const F8 gam2 = ld256(gbase + 2 * 256);
    const F8 gam3 = ld256(gbase + 3 * 256);

    // --- compute (float-domain selects; delta in {1,2,3,4}) ---
    F8 o;
#pragma unroll
    for (int c = 0; c < 8; c++) {
        const float dv = dl.v[c];
        const float hv = ha.v[c];
        const float f  = (dv == 1.0f) ? hv
                       : (dv == 2.0f) ? w1.v[c]
                       : (dv == 3.0f) ? w2.v[c] : w3.v[c];
        const float gv = (dv == 2.0f) ? gam1.v[c]
                       : (dv == 3.0f) ? gam2.v[c] : gam3.v[c];
        // dv==1 => f-hv==0, gv irrelevant
        o.v[c] = fmaf((1.0f - mm.v[c]) * gv, f - hv, hv);
    }

    st256(OUT + r * 256 + col8 * 8, o);
}

extern "C" void kernel_launch(void* const* d_in, const int* in_sizes, int n_in,
                              void* d_out, int out_size) {
    const float* h_a    = (const float*)d_in[0];
    const float* deltas = (const float*)d_in[1];
    const float* Mmask  = (const float*)d_in[2];
    const float* W      = (const float*)d_in[3];
    const float* b      = (const float*)d_in[4];
    float* out = (float*)d_out;

    gamma_precompute_kernel<<<1, 256>>>(W, b);

    // PDL: decay launches/overlaps while gamma runs; decay grid-dep-syncs
    // before touching the table.
    cudaLaunchAttribute attr[1];
    attr[0].id = cudaLaunchAttributeProgrammaticStreamSerialization;
    attr[0].val.programmaticStreamSerializationAllowed = 1;
    cudaLaunchConfig_t cfg = {};
    cfg.gridDim = dim3(BLOCKS);
    cfg.blockDim = dim3(THREADS);
    cfg.dynamicSmemBytes = 0;
    cfg.stream = 0;
    cfg.attrs = attr;
    cfg.numAttrs = 1;
    cudaLaunchKernelEx(&cfg, decay_kernel, h_a, deltas, Mmask, out);
}

// round 14
// speedup vs baseline: 1.1242x; 1.1242x over previous
#include <cuda_runtime.h>

// TemporalDecay: out = h + (1-m)*g*(h_fwd - h),
//   g = exp(-relu(delta*W + b)),  delta integer in [1,4],
//   h_fwd[b,t,j] = h_a[b, t-(delta-1), j]   (<= 3 rows back).
//
// R14 = R7 body (SEG=2 register halo, batched 12-load MLP, gamma table, PDL,
// 56 regs) at finer residency granularity: 96-thread blocks with
// __launch_bounds__(96,12) -> same 36-warp/SM ceiling (65536/1152 = 56.9 regs)
// but 3-warp quanta pack/drain with less block-quantization tail than R7's
// 4-warp x 9 blocks. v8 accesses (R13) and L2 policies (R12) measured
// regressive/neutral and are dropped.

static constexpr int Bq = 32, Tq = 2048;
static constexpr int C4 = 64;          // float4s per 256-channel row
static constexpr int SEG = 2;          // t rows per thread
static constexpr int NSEG = Tq / SEG;  // 1024
static constexpr int THREADS = 96;
static constexpr int TOTAL = Bq * C4 * NSEG;             // 2,097,152 threads of work
static constexpr int BLOCKS = (TOTAL + THREADS - 1) / THREADS;  // 21846

// gamma[d-1][channel], 4 rows of 64 float4s (only rows 1..3 read by decay).
__device__ float4 g_gamma4[4 * C4];

__global__ void gamma_precompute_kernel(const float* __restrict__ W,
                                        const float* __restrict__ bias) {
    cudaTriggerProgrammaticLaunchCompletion();
    int j = threadIdx.x;  // 0..255 channel
    float w = W[j];
    float bb = bias[j];
    float* gf = (float*)g_gamma4;
#pragma unroll
    for (int dm = 0; dm < 4; dm++) {
        float x = fmaxf(fmaf((float)(dm + 1), w, bb), 0.0f);
        gf[dm * 256 + j] = __expf(-x);
    }
}

__global__ void __launch_bounds__(THREADS, 12) decay_kernel(
    const float4* __restrict__ H,      // h_a  [B*T*64] float4
    const float4* __restrict__ DL,     // deltas [B*T*16] float4
    const float4* __restrict__ MM,     // mask   [B*T*16] float4
    float4* __restrict__ OUT)
{
    const int g = blockIdx.x * THREADS + threadIdx.x;
    if (g >= TOTAL) return;

    const int col4 = g & 63;
    const int seg  = (g >> 6) & (NSEG - 1);
    const int bb   = g >> 16;
    const int t0   = seg * SEG;

    const int rb    = bb * Tq * C4 + col4;              // row base into H/OUT
    const int dbase = (bb * Tq + t0) * 16 + (col4 & 15);

    // --- batched, fully independent loads (12 in flight; overlap PDL) ---
    // R[k] holds row t0-3+k (k=0..2 halo, clamped; k=3..4 the 2 output rows).
    float4 R[5];
#pragma unroll
    for (int k = 0; k < 3; k++) {
        const int t = max(t0 - 3 + k, 0);   // clamped halo never selected at t0==0
        R[k] = __ldg(H + rb + t * C4);
    }
#pragma unroll
    for (int s = 0; s < SEG; s++)
        R[3 + s] = __ldg(H + rb + (t0 + s) * C4);

    float4 dl[SEG], mm[SEG];
#pragma unroll
    for (int s = 0; s < SEG; s++) {
        dl[s] = __ldg(DL + dbase + s * 16);
        mm[s] = __ldg(MM + dbase + s * 16);
    }

    // --- wait for gamma table, then load this thread's 3 float4s (L1-hot) ---
    cudaGridDependencySynchronize();
    const float4 gam1 = __ldg(g_gamma4 + 1 * C4 + col4);
    const float4 gam2 = __ldg(g_gamma4 + 2 * C4 + col4);
    const float4 gam3 = __ldg(g_gamma4 + 3 * C4 + col4);

    // --- compute + store (float-domain selects; delta in {1,2,3,4}) ---
#pragma unroll
    for (int s = 0; s < SEG; s++) {
        const float4 ha = R[3 + s];
        const float4 w1 = R[2 + s];
        const float4 w2 = R[1 + s];
        const float4 w3 = R[0 + s];
        float4 o;
#define PROC(c)                                                           \
        {                                                                 \
            const float dv = dl[s].c;                                     \
            const float f  = (dv == 1.0f) ? ha.c                          \
                           : (dv == 2.0f) ? w1.c                          \
                           : (dv == 3.0f) ? w2.c : w3.c;                  \
            const float gv = (dv == 2.0f) ? gam1.c                        \
                           : (dv == 3.0f) ? gam2.c : gam3.c;              \
            /* dv==1 => f-ha==0, gv irrelevant */                         \
            o.c = fmaf((1.0f - mm[s].c) * gv, f - ha.c, ha.c);            \
        }
        PROC(x) PROC(y) PROC(z) PROC(w)
#undef PROC
        OUT[rb + (t0 + s) * C4] = o;
    }
}

extern "C" void kernel_launch(void* const* d_in, const int* in_sizes, int n_in,
                              void* d_out, int out_size) {
    const float4* h_a    = (const float4*)d_in[0];
    const float4* deltas = (const float4*)d_in[1];
    const float4* Mmask  = (const float4*)d_in[2];
    const float*  W      = (const float*)d_in[3];
    const float*  b      = (const float*)d_in[4];
    float4* out = (float4*)d_out;

    gamma_precompute_kernel<<<1, 256>>>(W, b);

    // PDL: decay launches/overlaps while gamma runs; decay grid-dep-syncs
    // before touching the table.
    cudaLaunchAttribute attr[1];
    attr[0].id = cudaLaunchAttributeProgrammaticStreamSerialization;
    attr[0].val.programmaticStreamSerializationAllowed = 1;
    cudaLaunchConfig_t cfg = {};
    cfg.gridDim = dim3(BLOCKS);
    cfg.blockDim = dim3(THREADS);
    cfg.dynamicSmemBytes = 0;
    cfg.stream = 0;
    cfg.attrs = attr;
    cfg.numAttrs = 1;
    cudaLaunchKernelEx(&cfg, decay_kernel, h_a, deltas, Mmask, out);
}